// round 5
// baseline (speedup 1.0000x reference)
#include <cuda_runtime.h>
#include <cstdint>
#include <cstddef>

#define BB 2
#define CC 128
#define LL 4096
#define DI 256
#define NS 16
#define RK 8
#define NCH 16     // chunks along L
#define TCH 256    // chunk length

typedef unsigned long long ull;

// ---------------- scratch (static device globals; no allocation) ----------------
__device__ float g_x3t  [2*BB*CC*LL];
__device__ float g_xpre [2*BB*DI*LL];
__device__ float g_z    [2*BB*DI*LL];
__device__ float g_xconv[2*BB*DI*LL];
__device__ float g_delta[2*BB*DI*LL];
__device__ float g_xdbl [2*BB*40*LL];      // W_x @ xconv, (bz, 40, l)
__device__ float g_Bt   [2*BB*LL*NS];      // blocked: (bz, l/16, n, l%16)
__device__ float g_Ct   [2*BB*LL*NS];      // blocked: (bz, l/16, n, l%16)
__device__ float g_y    [2*BB*DI*LL];
__device__ float g_P    [2*BB*DI*NCH*NS];
__device__ float g_E    [2*BB*DI*NCH*NS];
__device__ float g_c    [2*BB*DI*NCH*NS];

__device__ __forceinline__ ull pack2(float v) {
    ull r; asm("mov.b64 %0, {%1, %1};" : "=l"(r) : "f"(v)); return r;
}
#define FFMA2(c, a, b) asm("fma.rn.f32x2 %0, %1, %2, %0;" : "+l"(c) : "l"(a), "l"(b))

// ---------------- K1: layernorm over C, transpose to (b,c,l) ----------------
__global__ __launch_bounds__(256) void ln_kernel(
    const float* __restrict__ pan, const float* __restrict__ ms,
    const float* __restrict__ nw0, const float* __restrict__ nb0,
    const float* __restrict__ nw1, const float* __restrict__ nb1)
{
    const int br = blockIdx.z;
    const int b  = blockIdx.y;
    const int l0 = blockIdx.x * 32;
    const float* src = br ? ms  : pan;
    const float* wv  = br ? nw1 : nw0;
    const float* bv  = br ? nb1 : nb0;

    __shared__ float s[32][129];
    __shared__ float mu_s[32], rs_s[32];

    const float* base = src + (size_t)b * CC * LL + l0;
    for (int i = threadIdx.x; i < CC * 32; i += 256) {
        int c = i >> 5, col = i & 31;
        s[col][c] = base[(size_t)c * LL + col];
    }
    __syncthreads();

    int lloc = threadIdx.x >> 3;
    int part = threadIdx.x & 7;
    float sum = 0.f, sq = 0.f;
    for (int c = part * 16; c < part * 16 + 16; c++) {
        float v = s[lloc][c];
        sum += v; sq += v * v;
    }
    for (int off = 4; off; off >>= 1) {
        sum += __shfl_xor_sync(0xffffffffu, sum, off);
        sq  += __shfl_xor_sync(0xffffffffu, sq,  off);
    }
    if (part == 0) {
        float mu = sum * (1.f / 128.f);
        float var = sq * (1.f / 128.f) - mu * mu;
        mu_s[lloc] = mu;
        rs_s[lloc] = rsqrtf(var + 1e-5f);
    }
    __syncthreads();

    float* dst = g_x3t + ((size_t)(br * BB + b) * CC) * LL + l0;
    for (int i = threadIdx.x; i < CC * 32; i += 256) {
        int c = i >> 5, col = i & 31;
        float v = (s[col][c] - mu_s[col]) * rs_s[col] * wv[c] + bv[c];
        dst[(size_t)c * LL + col] = v;
    }
}

// ---------------- GEMM: packed f32x2, 128x128 tile, 8x8/thread ----------------
template<int K, int MODE>
__global__ __launch_bounds__(256, 2) void gemm_kernel(
    const float* __restrict__ Wa0, const float* __restrict__ Wa1,
    const float* __restrict__ Wb0, const float* __restrict__ Wb1,
    float* __restrict__ Cout)
{
    const int bz = blockIdx.z;
    const int br = bz >> 1;
    const int mt = blockIdx.y;
    const int n0 = blockIdx.x * 128;

    const float* A;
    float* Cp;
    if (MODE == 0) {
        int sel = mt >> 1;
        A = sel ? (br ? Wb1 : Wb0) : (br ? Wa1 : Wa0);
        A += (size_t)(mt & 1) * 128 * K;
        Cp = (sel ? g_z : g_xpre) + (size_t)bz * DI * LL + (size_t)(mt & 1) * 128 * LL;
    } else {
        A = br ? Wa1 : Wa0;
        Cp = Cout + (size_t)bz * CC * LL;
    }
    const float* Bp = ((MODE == 0) ? g_x3t : g_y) + (size_t)bz * K * LL;

    __shared__ ull   As[2][16][128];
    __shared__ float Bs[2][16][128];

    const int tid = threadIdx.x;
    const int tn = tid & 15, tm = tid >> 4;
    const int ar = tid >> 2;
    const int aq = (tid & 3) * 4;
    const int bk = tid >> 4;
    const int bn = (tid & 15) * 4;

    ull acc[8][4];
#pragma unroll
    for (int i = 0; i < 8; i++)
#pragma unroll
        for (int j = 0; j < 4; j++) acc[i][j] = 0ull;

    float4 pa0, pa1, pb0, pb1;
    pa0 = *(const float4*)&A[(size_t)ar * K + aq];
    pa1 = *(const float4*)&A[(size_t)(ar + 64) * K + aq];
    pb0 = *(const float4*)&Bp[(size_t)bk * LL + n0 + bn];
    pb1 = *(const float4*)&Bp[(size_t)bk * LL + n0 + bn + 64];

    {
        As[0][aq + 0][ar] = pack2(pa0.x); As[0][aq + 1][ar] = pack2(pa0.y);
        As[0][aq + 2][ar] = pack2(pa0.z); As[0][aq + 3][ar] = pack2(pa0.w);
        As[0][aq + 0][ar + 64] = pack2(pa1.x); As[0][aq + 1][ar + 64] = pack2(pa1.y);
        As[0][aq + 2][ar + 64] = pack2(pa1.z); As[0][aq + 3][ar + 64] = pack2(pa1.w);
        *(float4*)&Bs[0][bk][bn] = pb0;
        *(float4*)&Bs[0][bk][bn + 64] = pb1;
    }
    __syncthreads();

    const int KT = K / 16;
    for (int kt = 0; kt < KT; kt++) {
        const int cur = kt & 1;
        if (kt + 1 < KT) {
            const int ko = (kt + 1) * 16;
            pa0 = *(const float4*)&A[(size_t)ar * K + ko + aq];
            pa1 = *(const float4*)&A[(size_t)(ar + 64) * K + ko + aq];
            pb0 = *(const float4*)&Bp[(size_t)(ko + bk) * LL + n0 + bn];
            pb1 = *(const float4*)&Bp[(size_t)(ko + bk) * LL + n0 + bn + 64];
        }
#pragma unroll
        for (int k = 0; k < 16; k++) {
            ulonglong2 a01 = *(const ulonglong2*)&As[cur][k][tm * 4];
            ulonglong2 a23 = *(const ulonglong2*)&As[cur][k][tm * 4 + 2];
            ulonglong2 a45 = *(const ulonglong2*)&As[cur][k][64 + tm * 4];
            ulonglong2 a67 = *(const ulonglong2*)&As[cur][k][64 + tm * 4 + 2];
            ulonglong2 bA  = *(const ulonglong2*)&Bs[cur][k][tn * 4];
            ulonglong2 bB  = *(const ulonglong2*)&Bs[cur][k][64 + tn * 4];
            ull a[8] = {a01.x, a01.y, a23.x, a23.y, a45.x, a45.y, a67.x, a67.y};
            ull b[4] = {bA.x, bA.y, bB.x, bB.y};
#pragma unroll
            for (int i = 0; i < 8; i++)
#pragma unroll
                for (int j = 0; j < 4; j++)
                    FFMA2(acc[i][j], a[i], b[j]);
        }
        if (kt + 1 < KT) {
            const int nxt = cur ^ 1;
            As[nxt][aq + 0][ar] = pack2(pa0.x); As[nxt][aq + 1][ar] = pack2(pa0.y);
            As[nxt][aq + 2][ar] = pack2(pa0.z); As[nxt][aq + 3][ar] = pack2(pa0.w);
            As[nxt][aq + 0][ar + 64] = pack2(pa1.x); As[nxt][aq + 1][ar + 64] = pack2(pa1.y);
            As[nxt][aq + 2][ar + 64] = pack2(pa1.z); As[nxt][aq + 3][ar + 64] = pack2(pa1.w);
            *(float4*)&Bs[nxt][bk][bn] = pb0;
            *(float4*)&Bs[nxt][bk][bn + 64] = pb1;
        }
        __syncthreads();
    }

#pragma unroll
    for (int i = 0; i < 8; i++) {
        int r = (i < 4) ? (tm * 4 + i) : (64 + tm * 4 + (i - 4));
        *(float4*)&Cp[(size_t)r * LL + n0 + tn * 4]      = *(float4*)&acc[i][0];
        *(float4*)&Cp[(size_t)r * LL + n0 + 64 + tn * 4] = *(float4*)&acc[i][2];
    }
}

// ---------------- K3: causal depthwise conv1d (k=4) + bias + silu, x4 vectorized ----------------
__global__ __launch_bounds__(256) void conv_kernel(
    const float* __restrict__ cw0, const float* __restrict__ cb0,
    const float* __restrict__ cw1, const float* __restrict__ cb1)
{
    int idx4 = blockIdx.x * 256 + threadIdx.x;
    int lq = idx4 & (LL / 4 - 1);
    int rest = idx4 >> 10;
    int e = rest & (DI - 1);
    int br = rest >> 9;
    float4 w = *(const float4*)((br ? cw1 : cw0) + e * 4);
    float bias = (br ? cb1 : cb0)[e];
    const float* xp = g_xpre + (size_t)rest * LL;
    int l0 = lq * 4;
    float4 cur = *(const float4*)&xp[l0];
    float pm3 = 0.f, pm2 = 0.f, pm1 = 0.f;
    if (l0 > 0) {
        float4 pv = *(const float4*)&xp[l0 - 4];
        pm3 = pv.y; pm2 = pv.z; pm1 = pv.w;
    }
    float x0 = cur.x, x1 = cur.y, x2 = cur.z, x3 = cur.w;
    float o0 = bias + w.x * pm3 + w.y * pm2 + w.z * pm1 + w.w * x0;
    float o1 = bias + w.x * pm2 + w.y * pm1 + w.z * x0  + w.w * x1;
    float o2 = bias + w.x * pm1 + w.y * x0  + w.z * x1  + w.w * x2;
    float o3 = bias + w.x * x0  + w.y * x1  + w.z * x2  + w.w * x3;
    float4 out;
    out.x = o0 / (1.f + __expf(-o0));
    out.y = o1 / (1.f + __expf(-o1));
    out.z = o2 / (1.f + __expf(-o2));
    out.w = o3 / (1.f + __expf(-o3));
    *(float4*)&g_xconv[(size_t)rest * LL + l0] = out;
}

// ---------------- K4a: xdbl = W_x @ xconv  (M=40, K=256, N=4096 per bz) ----------------
__global__ __launch_bounds__(256) void xdbl_gemm_kernel(
    const float* __restrict__ Wx0, const float* __restrict__ Wx1)
{
    const int bz = blockIdx.y;
    const int br = bz >> 1;
    const int n0 = blockIdx.x * 128;
    const float* A = br ? Wx1 : Wx0;                         // 40 x 256
    const float* Bp = g_xconv + (size_t)bz * DI * LL;
    float* Cp = g_xdbl + (size_t)bz * 40 * LL;

    __shared__ ull   As[16][40];
    __shared__ float Bs[16][132];

    const int tid = threadIdx.x;
    const int tn = tid & 31;      // 32 col-groups of 4
    const int tm = tid >> 5;      // 8 row-groups of 5
    const int bk = tid >> 4;
    const int bn = (tid & 15) * 8;

    ull acc[5][2];
#pragma unroll
    for (int i = 0; i < 5; i++) { acc[i][0] = 0ull; acc[i][1] = 0ull; }

    for (int k0 = 0; k0 < DI; k0 += 16) {
        __syncthreads();
        if (tid < 160) {
            int row = tid >> 2, kq = (tid & 3) * 4;
            float4 av = *(const float4*)&A[(size_t)row * DI + k0 + kq];
            As[kq + 0][row] = pack2(av.x); As[kq + 1][row] = pack2(av.y);
            As[kq + 2][row] = pack2(av.z); As[kq + 3][row] = pack2(av.w);
        }
        *(float4*)&Bs[bk][bn]     = *(const float4*)&Bp[(size_t)(k0 + bk) * LL + n0 + bn];
        *(float4*)&Bs[bk][bn + 4] = *(const float4*)&Bp[(size_t)(k0 + bk) * LL + n0 + bn + 4];
        __syncthreads();
#pragma unroll
        for (int k = 0; k < 16; k++) {
            ulonglong2 bp = *(const ulonglong2*)&Bs[k][tn * 4];
            ull b0 = bp.x, b1 = bp.y;
#pragma unroll
            for (int i = 0; i < 5; i++) {
                ull av = As[k][tm * 5 + i];
                FFMA2(acc[i][0], av, b0);
                FFMA2(acc[i][1], av, b1);
            }
        }
    }
#pragma unroll
    for (int i = 0; i < 5; i++)
        *(float4*)&Cp[(size_t)(tm * 5 + i) * LL + n0 + tn * 4] = *(float4*)&acc[i][0];
}

// ---------------- K4b: delta = softplus(W_dt@dt_low + b) ; Bt/Ct blocked transpose ----------------
__global__ __launch_bounds__(256) void k4b_kernel(
    const float* __restrict__ Wdt0, const float* __restrict__ Wdt1,
    const float* __restrict__ bdt0, const float* __restrict__ bdt1)
{
    const int bz = blockIdx.y;
    const int br = bz >> 1;
    const int l0 = blockIdx.x * 64;
    const float* Wdt = br ? Wdt1 : Wdt0;
    const float* bdt = br ? bdt1 : bdt0;

    __shared__ float xds[40][65];
    __shared__ float Wdts[DI * RK];
    __shared__ float bdts[DI];

    const int tid = threadIdx.x;
    for (int i = tid; i < DI * RK; i += 256) Wdts[i] = Wdt[i];
    bdts[tid] = bdt[tid];

    const float* xd = g_xdbl + (size_t)bz * 40 * LL + l0;
    for (int i = tid; i < 40 * 16; i += 256) {          // 640 float4 loads
        int r = i >> 4, c4 = (i & 15) * 4;
        float4 v = *(const float4*)&xd[(size_t)r * LL + c4];
        xds[r][c4] = v.x; xds[r][c4 + 1] = v.y; xds[r][c4 + 2] = v.z; xds[r][c4 + 3] = v.w;
    }
    __syncthreads();

    // Bt/Ct blocked layout: (bz, l/16, n, l%16)
    {
        float* Bb = g_Bt + (size_t)bz * LL * NS;
        float* Cb = g_Ct + (size_t)bz * LL * NS;
        for (int i = tid; i < 1024; i += 256) {
            int n = i >> 6, l = i & 63;
            size_t o = (size_t)(((l0 + l) >> 4) * NS + n) * 16 + (l & 15);
            Bb[o] = xds[8 + n][l];
            Cb[o] = xds[24 + n][l];
        }
    }
    // delta
    const int lcol = tid & 63, rg = tid >> 6;
    float dtl[RK];
#pragma unroll
    for (int r = 0; r < RK; r++) dtl[r] = xds[r][lcol];
    float* dp = g_delta + (size_t)bz * DI * LL + l0 + lcol;
#pragma unroll 4
    for (int jj = 0; jj < 64; jj++) {
        int d = rg + jj * 4;
        float a = bdts[d];
#pragma unroll
        for (int r = 0; r < RK; r++)
            a = fmaf(Wdts[d * RK + r], dtl[r], a);
        float sp = fmaxf(a, 0.f) + __logf(1.f + __expf(-fabsf(a)));
        dp[(size_t)d * LL] = sp;
    }
}

// ---------------- K5a: chunk summaries ----------------
__global__ __launch_bounds__(128) void scan1_kernel(const float* __restrict__ A_log)
{
    const int lane = threadIdx.x & 31;
    const int hw = blockIdx.x * 8 + (threadIdx.x >> 5) * 2 + (lane >> 4);
    const int ch = hw >> 4;
    const int chunk = hw & 15;
    const int d  = ch & 255;
    const int bz = ch >> 8;
    const int n  = lane & 15;
    const int half = lane & 16;

    const float An = -__expf(A_log[d * NS + n]);
    const float* dl_p = g_delta + (size_t)ch * LL;
    const float* x_p  = g_xconv + (size_t)ch * LL;
    const float* B_p  = g_Bt + (size_t)bz * LL * NS;

    float h = 0.f, pa = 1.f;
    const int lbeg = chunk * TCH;
    for (int l0 = lbeg; l0 < lbeg + TCH; l0 += 16) {
        float dv = dl_p[l0 + n];
        float xv = x_p[l0 + n];
        float duv = dv * xv;
        float Bv[16];
        {
            const float* bb = &B_p[(size_t)((l0 >> 4) * NS + n) * 16];
            *(float4*)&Bv[0]  = *(const float4*)&bb[0];
            *(float4*)&Bv[4]  = *(const float4*)&bb[4];
            *(float4*)&Bv[8]  = *(const float4*)&bb[8];
            *(float4*)&Bv[12] = *(const float4*)&bb[12];
        }
#pragma unroll
        for (int s = 0; s < 16; s++) {
            float dl = __shfl_sync(0xffffffffu, dv,  half + s);
            float du = __shfl_sync(0xffffffffu, duv, half + s);
            float a = __expf(dl * An);
            h = fmaf(a, h, du * Bv[s]);
            pa *= a;
        }
    }
    size_t o = ((size_t)ch * NCH + chunk) * NS + n;
    g_P[o] = pa;
    g_E[o] = h;
}

// ---------------- K5b: stitch carries ----------------
__global__ __launch_bounds__(256) void scan2_kernel()
{
    int t = blockIdx.x * 256 + threadIdx.x;
    int ch = t >> 4;
    int n  = t & 15;
    float c = 0.f;
#pragma unroll
    for (int j = 0; j < NCH; j++) {
        size_t o = ((size_t)ch * NCH + j) * NS + n;
        g_c[o] = c;
        c = fmaf(g_P[o], c, g_E[o]);
    }
}

// ---------------- K5c: full scan + tree reduce + fused epilogue ----------------
__global__ __launch_bounds__(128) void scan3_kernel(
    const float* __restrict__ A_log,
    const float* __restrict__ D0, const float* __restrict__ D1)
{
    const int lane = threadIdx.x & 31;
    const int hw = blockIdx.x * 8 + (threadIdx.x >> 5) * 2 + (lane >> 4);
    const int ch = hw >> 4;
    const int chunk = hw & 15;
    const int br = ch >> 9;
    const int d  = ch & 255;
    const int bz = ch >> 8;
    const int n  = lane & 31 & 15;
    const int half = lane & 16;

    const float An = -__expf(A_log[d * NS + n]);
    const float Dd = (br ? D1 : D0)[d];

    const float* dl_p = g_delta + (size_t)ch * LL;
    const float* x_p  = g_xconv + (size_t)ch * LL;
    const float* z_p  = g_z     + (size_t)ch * LL;
    const float* B_p  = g_Bt + (size_t)bz * LL * NS;
    const float* C_p  = g_Ct + (size_t)bz * LL * NS;
    float* y_p = g_y + (size_t)ch * LL;

    float h = g_c[((size_t)ch * NCH + chunk) * NS + n];
    const int lbeg = chunk * TCH;
    for (int l0 = lbeg; l0 < lbeg + TCH; l0 += 16) {
        float dv = dl_p[l0 + n];
        float xv = x_p[l0 + n];
        float zv = z_p[l0 + n];
        float duv = dv * xv;
        float sv = zv / (1.f + __expf(-zv));
        float ev = Dd * xv;

        float Bv[16], Cv[16];
        {
            const size_t bo = (size_t)((l0 >> 4) * NS + n) * 16;
            const float* bb = &B_p[bo];
            const float* cc = &C_p[bo];
            *(float4*)&Bv[0]  = *(const float4*)&bb[0];
            *(float4*)&Bv[4]  = *(const float4*)&bb[4];
            *(float4*)&Bv[8]  = *(const float4*)&bb[8];
            *(float4*)&Bv[12] = *(const float4*)&bb[12];
            *(float4*)&Cv[0]  = *(const float4*)&cc[0];
            *(float4*)&Cv[4]  = *(const float4*)&cc[4];
            *(float4*)&Cv[8]  = *(const float4*)&cc[8];
            *(float4*)&Cv[12] = *(const float4*)&cc[12];
        }

        float v[16];
#pragma unroll
        for (int s = 0; s < 16; s++) {
            float dl = __shfl_sync(0xffffffffu, dv,  half + s);
            float du = __shfl_sync(0xffffffffu, duv, half + s);
            float a = __expf(dl * An);
            h = fmaf(a, h, du * Bv[s]);
            v[s] = h * Cv[s];
        }
        {
            bool hi = (n & 8) != 0;
#pragma unroll
            for (int j = 0; j < 8; j++) {
                float send = hi ? v[j] : v[j + 8];
                float recv = __shfl_xor_sync(0xffffffffu, send, 8);
                v[j] = (hi ? v[j + 8] : v[j]) + recv;
            }
        }
        {
            bool hi = (n & 4) != 0;
#pragma unroll
            for (int j = 0; j < 4; j++) {
                float send = hi ? v[j] : v[j + 4];
                float recv = __shfl_xor_sync(0xffffffffu, send, 4);
                v[j] = (hi ? v[j + 4] : v[j]) + recv;
            }
        }
        {
            bool hi = (n & 2) != 0;
#pragma unroll
            for (int j = 0; j < 2; j++) {
                float send = hi ? v[j] : v[j + 2];
                float recv = __shfl_xor_sync(0xffffffffu, send, 2);
                v[j] = (hi ? v[j + 2] : v[j]) + recv;
            }
        }
        {
            bool hi = (n & 1) != 0;
            float send = hi ? v[0] : v[1];
            float recv = __shfl_xor_sync(0xffffffffu, send, 1);
            v[0] = (hi ? v[1] : v[0]) + recv;
        }
        y_p[l0 + n] = (v[0] + ev) * sv;
    }
}

// ---------------- launch ----------------
extern "C" void kernel_launch(void* const* d_in, const int* in_sizes, int n_in,
                              void* d_out, int out_size)
{
    const float* pan     = (const float*)d_in[0];
    const float* ms      = (const float*)d_in[1];
    const float* nw_pan  = (const float*)d_in[2];
    const float* nb_pan  = (const float*)d_in[3];
    const float* nw_ms   = (const float*)d_in[4];
    const float* nb_ms   = (const float*)d_in[5];
    const float* Win_pan = (const float*)d_in[6];
    const float* Win_ms  = (const float*)d_in[7];
    const float* Wz_pan  = (const float*)d_in[8];
    const float* Wz_ms   = (const float*)d_in[9];
    const float* cw_pan  = (const float*)d_in[10];
    const float* cb_pan  = (const float*)d_in[11];
    const float* cw_ms   = (const float*)d_in[12];
    const float* cb_ms   = (const float*)d_in[13];
    const float* Wx_pan  = (const float*)d_in[14];
    const float* Wx_ms   = (const float*)d_in[15];
    const float* Wdt_pan = (const float*)d_in[16];
    const float* Wdt_ms  = (const float*)d_in[17];
    const float* bdt_pan = (const float*)d_in[18];
    const float* bdt_ms  = (const float*)d_in[19];
    const float* A_log   = (const float*)d_in[20];
    const float* D_pan   = (const float*)d_in[21];
    const float* D_ms    = (const float*)d_in[22];
    const float* Wout_pan= (const float*)d_in[23];
    const float* Wout_ms = (const float*)d_in[24];
    float* out = (float*)d_out;

    ln_kernel<<<dim3(LL / 32, BB, 2), 256>>>(pan, ms, nw_pan, nb_pan, nw_ms, nb_ms);

    gemm_kernel<CC, 0><<<dim3(LL / 128, 4, 2 * BB), 256>>>(
        Win_pan, Win_ms, Wz_pan, Wz_ms, nullptr);

    conv_kernel<<<(2 * BB * DI * LL / 4) / 256, 256>>>(cw_pan, cb_pan, cw_ms, cb_ms);

    xdbl_gemm_kernel<<<dim3(LL / 128, 2 * BB), 256>>>(Wx_pan, Wx_ms);
    k4b_kernel<<<dim3(LL / 64, 2 * BB), 256>>>(Wdt_pan, Wdt_ms, bdt_pan, bdt_ms);

    scan1_kernel<<<(2 * BB * DI * NCH) / 8, 128>>>(A_log);
    scan2_kernel<<<(2 * BB * DI * NS) / 256, 256>>>();
    scan3_kernel<<<(2 * BB * DI * NCH) / 8, 128>>>(A_log, D_pan, D_ms);

    gemm_kernel<DI, 2><<<dim3(LL / 128, 1, 2 * BB), 256>>>(
        Wout_pan, Wout_ms, nullptr, nullptr, out);
}

// round 6
// speedup vs baseline: 1.1145x; 1.1145x over previous
#include <cuda_runtime.h>
#include <cstdint>
#include <cstddef>

#define BB 2
#define CC 128
#define LL 4096
#define DI 256
#define NS 16
#define RK 8
#define NCH 16     // chunks along L
#define TCH 256    // chunk length

typedef unsigned long long ull;

// ---------------- scratch (static device globals; no allocation) ----------------
__device__ float g_x3t  [2*BB*CC*LL];
__device__ float g_xpre [2*BB*DI*LL];
__device__ float g_z    [2*BB*DI*LL];
__device__ float g_xconv[2*BB*DI*LL];
__device__ float g_delta[2*BB*DI*LL];
__device__ float g_xd0  [2*BB*40*LL];      // W_x @ xconv, K-half 0
__device__ float g_xd1  [2*BB*40*LL];      // W_x @ xconv, K-half 1
__device__ float g_Bt   [2*BB*LL*NS];      // blocked: (bz, l/16, n, l%16)
__device__ float g_Ct   [2*BB*LL*NS];      // blocked: (bz, l/16, n, l%16)
__device__ float g_y    [2*BB*DI*LL];
__device__ float g_P    [2*BB*DI*NCH*NS];
__device__ float g_E    [2*BB*DI*NCH*NS];
__device__ float g_c    [2*BB*DI*NCH*NS];

__device__ __forceinline__ ull pack2(float v) {
    ull r; asm("mov.b64 %0, {%1, %1};" : "=l"(r) : "f"(v)); return r;
}
#define FFMA2(c, a, b) asm("fma.rn.f32x2 %0, %1, %2, %0;" : "+l"(c) : "l"(a), "l"(b))

// ---------------- K1: layernorm over C, transpose to (b,c,l) ----------------
__global__ __launch_bounds__(256) void ln_kernel(
    const float* __restrict__ pan, const float* __restrict__ ms,
    const float* __restrict__ nw0, const float* __restrict__ nb0,
    const float* __restrict__ nw1, const float* __restrict__ nb1)
{
    const int br = blockIdx.z;
    const int b  = blockIdx.y;
    const int l0 = blockIdx.x * 32;
    const float* src = br ? ms  : pan;
    const float* wv  = br ? nw1 : nw0;
    const float* bv  = br ? nb1 : nb0;

    __shared__ float s[32][129];
    __shared__ float mu_s[32], rs_s[32];

    const float* base = src + (size_t)b * CC * LL + l0;
    for (int i = threadIdx.x; i < CC * 32; i += 256) {
        int c = i >> 5, col = i & 31;
        s[col][c] = base[(size_t)c * LL + col];
    }
    __syncthreads();

    int lloc = threadIdx.x >> 3;
    int part = threadIdx.x & 7;
    float sum = 0.f, sq = 0.f;
    for (int c = part * 16; c < part * 16 + 16; c++) {
        float v = s[lloc][c];
        sum += v; sq += v * v;
    }
    for (int off = 4; off; off >>= 1) {
        sum += __shfl_xor_sync(0xffffffffu, sum, off);
        sq  += __shfl_xor_sync(0xffffffffu, sq,  off);
    }
    if (part == 0) {
        float mu = sum * (1.f / 128.f);
        float var = sq * (1.f / 128.f) - mu * mu;
        mu_s[lloc] = mu;
        rs_s[lloc] = rsqrtf(var + 1e-5f);
    }
    __syncthreads();

    float* dst = g_x3t + ((size_t)(br * BB + b) * CC) * LL + l0;
    for (int i = threadIdx.x; i < CC * 32; i += 256) {
        int c = i >> 5, col = i & 31;
        float v = (s[col][c] - mu_s[col]) * rs_s[col] * wv[c] + bv[c];
        dst[(size_t)c * LL + col] = v;
    }
}

// ---------------- GEMM: f32x2, A staged as fp32 + reg-packed, 128x128 tile ----------------
template<int K, int MODE>
__global__ __launch_bounds__(256, 2) void gemm_kernel(
    const float* __restrict__ Wa0, const float* __restrict__ Wa1,
    const float* __restrict__ Wb0, const float* __restrict__ Wb1,
    float* __restrict__ Cout)
{
    const int bz = blockIdx.z;
    const int br = bz >> 1;
    const int mt = blockIdx.y;
    const int n0 = blockIdx.x * 128;

    const float* A;
    float* Cp;
    if (MODE == 0) {
        int sel = mt >> 1;
        A = sel ? (br ? Wb1 : Wb0) : (br ? Wa1 : Wa0);
        A += (size_t)(mt & 1) * 128 * K;
        Cp = (sel ? g_z : g_xpre) + (size_t)bz * DI * LL + (size_t)(mt & 1) * 128 * LL;
    } else {
        A = br ? Wa1 : Wa0;
        Cp = Cout + (size_t)bz * CC * LL;
    }
    const float* Bp = ((MODE == 0) ? g_x3t : g_y) + (size_t)bz * K * LL;

    __shared__ float As[2][16][128];
    __shared__ float Bs[2][16][128];

    const int tid = threadIdx.x;
    const int tn = tid & 15, tm = tid >> 4;
    const int ar = tid >> 2;
    const int aq = (tid & 3) * 4;
    const int bk = tid >> 4;
    const int bn = (tid & 15) * 4;

    ull acc[8][4];
#pragma unroll
    for (int i = 0; i < 8; i++)
#pragma unroll
        for (int j = 0; j < 4; j++) acc[i][j] = 0ull;

    float4 pa0, pa1, pb0, pb1;
    pa0 = *(const float4*)&A[(size_t)ar * K + aq];
    pa1 = *(const float4*)&A[(size_t)(ar + 64) * K + aq];
    pb0 = *(const float4*)&Bp[(size_t)bk * LL + n0 + bn];
    pb1 = *(const float4*)&Bp[(size_t)bk * LL + n0 + bn + 64];

    {
        As[0][aq + 0][ar] = pa0.x; As[0][aq + 1][ar] = pa0.y;
        As[0][aq + 2][ar] = pa0.z; As[0][aq + 3][ar] = pa0.w;
        As[0][aq + 0][ar + 64] = pa1.x; As[0][aq + 1][ar + 64] = pa1.y;
        As[0][aq + 2][ar + 64] = pa1.z; As[0][aq + 3][ar + 64] = pa1.w;
        *(float4*)&Bs[0][bk][bn] = pb0;
        *(float4*)&Bs[0][bk][bn + 64] = pb1;
    }
    __syncthreads();

    const int KT = K / 16;
    for (int kt = 0; kt < KT; kt++) {
        const int cur = kt & 1;
        if (kt + 1 < KT) {
            const int ko = (kt + 1) * 16;
            pa0 = *(const float4*)&A[(size_t)ar * K + ko + aq];
            pa1 = *(const float4*)&A[(size_t)(ar + 64) * K + ko + aq];
            pb0 = *(const float4*)&Bp[(size_t)(ko + bk) * LL + n0 + bn];
            pb1 = *(const float4*)&Bp[(size_t)(ko + bk) * LL + n0 + bn + 64];
        }
#pragma unroll
        for (int k = 0; k < 16; k++) {
            float2 a01f = *(const float2*)&As[cur][k][tm * 4];
            float2 a23f = *(const float2*)&As[cur][k][tm * 4 + 2];
            float2 a45f = *(const float2*)&As[cur][k][64 + tm * 4];
            float2 a67f = *(const float2*)&As[cur][k][64 + tm * 4 + 2];
            ulonglong2 bA  = *(const ulonglong2*)&Bs[cur][k][tn * 4];
            ulonglong2 bB  = *(const ulonglong2*)&Bs[cur][k][64 + tn * 4];
            ull a[8];
            a[0] = pack2(a01f.x); a[1] = pack2(a01f.y);
            a[2] = pack2(a23f.x); a[3] = pack2(a23f.y);
            a[4] = pack2(a45f.x); a[5] = pack2(a45f.y);
            a[6] = pack2(a67f.x); a[7] = pack2(a67f.y);
            ull b[4] = {bA.x, bA.y, bB.x, bB.y};
#pragma unroll
            for (int i = 0; i < 8; i++)
#pragma unroll
                for (int j = 0; j < 4; j++)
                    FFMA2(acc[i][j], a[i], b[j]);
        }
        if (kt + 1 < KT) {
            const int nxt = cur ^ 1;
            As[nxt][aq + 0][ar] = pa0.x; As[nxt][aq + 1][ar] = pa0.y;
            As[nxt][aq + 2][ar] = pa0.z; As[nxt][aq + 3][ar] = pa0.w;
            As[nxt][aq + 0][ar + 64] = pa1.x; As[nxt][aq + 1][ar + 64] = pa1.y;
            As[nxt][aq + 2][ar + 64] = pa1.z; As[nxt][aq + 3][ar + 64] = pa1.w;
            *(float4*)&Bs[nxt][bk][bn] = pb0;
            *(float4*)&Bs[nxt][bk][bn + 64] = pb1;
        }
        __syncthreads();
    }

#pragma unroll
    for (int i = 0; i < 8; i++) {
        int r = (i < 4) ? (tm * 4 + i) : (64 + tm * 4 + (i - 4));
        *(float4*)&Cp[(size_t)r * LL + n0 + tn * 4]      = *(float4*)&acc[i][0];
        *(float4*)&Cp[(size_t)r * LL + n0 + 64 + tn * 4] = *(float4*)&acc[i][2];
    }
}

// ---------------- K3: causal depthwise conv1d (k=4) + bias + silu, x4 vectorized ----------------
__global__ __launch_bounds__(256) void conv_kernel(
    const float* __restrict__ cw0, const float* __restrict__ cb0,
    const float* __restrict__ cw1, const float* __restrict__ cb1)
{
    int idx4 = blockIdx.x * 256 + threadIdx.x;
    int lq = idx4 & (LL / 4 - 1);
    int rest = idx4 >> 10;
    int e = rest & (DI - 1);
    int br = rest >> 9;
    float4 w = *(const float4*)((br ? cw1 : cw0) + e * 4);
    float bias = (br ? cb1 : cb0)[e];
    const float* xp = g_xpre + (size_t)rest * LL;
    int l0 = lq * 4;
    float4 cur = *(const float4*)&xp[l0];
    float pm3 = 0.f, pm2 = 0.f, pm1 = 0.f;
    if (l0 > 0) {
        float4 pv = *(const float4*)&xp[l0 - 4];
        pm3 = pv.y; pm2 = pv.z; pm1 = pv.w;
    }
    float x0 = cur.x, x1 = cur.y, x2 = cur.z, x3 = cur.w;
    float o0 = bias + w.x * pm3 + w.y * pm2 + w.z * pm1 + w.w * x0;
    float o1 = bias + w.x * pm2 + w.y * pm1 + w.z * x0  + w.w * x1;
    float o2 = bias + w.x * pm1 + w.y * x0  + w.z * x1  + w.w * x2;
    float o3 = bias + w.x * x0  + w.y * x1  + w.z * x2  + w.w * x3;
    float4 out;
    out.x = o0 / (1.f + __expf(-o0));
    out.y = o1 / (1.f + __expf(-o1));
    out.z = o2 / (1.f + __expf(-o2));
    out.w = o3 / (1.f + __expf(-o3));
    *(float4*)&g_xconv[(size_t)rest * LL + l0] = out;
}

// ---------------- K4a: xdbl halves = W_x[:,half] @ xconv[half]  ----------------
// grid (LL/128, 2*BB, 2 halves); each half -> g_xd0 / g_xd1
__global__ __launch_bounds__(256) void xdbl_gemm_kernel(
    const float* __restrict__ Wx0, const float* __restrict__ Wx1)
{
    const int bz = blockIdx.y;
    const int br = bz >> 1;
    const int half = blockIdx.z;
    const int n0 = blockIdx.x * 128;
    const float* A = (br ? Wx1 : Wx0) + half * 128;          // 40 x 256, column offset
    const float* Bp = g_xconv + (size_t)bz * DI * LL + (size_t)half * 128 * LL;
    float* Cp = (half ? g_xd1 : g_xd0) + (size_t)bz * 40 * LL;

    __shared__ ull   As[16][40];
    __shared__ float Bs[16][132];

    const int tid = threadIdx.x;
    const int tn = tid & 31;
    const int tm = tid >> 5;
    const int bk = tid >> 4;
    const int bn = (tid & 15) * 8;

    ull acc[5][2];
#pragma unroll
    for (int i = 0; i < 5; i++) { acc[i][0] = 0ull; acc[i][1] = 0ull; }

    for (int k0 = 0; k0 < 128; k0 += 16) {
        __syncthreads();
        if (tid < 160) {
            int row = tid >> 2, kq = (tid & 3) * 4;
            float4 av = *(const float4*)&A[(size_t)row * DI + k0 + kq];
            As[kq + 0][row] = pack2(av.x); As[kq + 1][row] = pack2(av.y);
            As[kq + 2][row] = pack2(av.z); As[kq + 3][row] = pack2(av.w);
        }
        *(float4*)&Bs[bk][bn]     = *(const float4*)&Bp[(size_t)(k0 + bk) * LL + n0 + bn];
        *(float4*)&Bs[bk][bn + 4] = *(const float4*)&Bp[(size_t)(k0 + bk) * LL + n0 + bn + 4];
        __syncthreads();
#pragma unroll
        for (int k = 0; k < 16; k++) {
            ulonglong2 bp = *(const ulonglong2*)&Bs[k][tn * 4];
            ull b0 = bp.x, b1 = bp.y;
#pragma unroll
            for (int i = 0; i < 5; i++) {
                ull av = As[k][tm * 5 + i];
                FFMA2(acc[i][0], av, b0);
                FFMA2(acc[i][1], av, b1);
            }
        }
    }
#pragma unroll
    for (int i = 0; i < 5; i++)
        *(float4*)&Cp[(size_t)(tm * 5 + i) * LL + n0 + tn * 4] = *(float4*)&acc[i][0];
}

// ---------------- K4b: sum halves; delta softplus; Bt/Ct blocked transpose ----------------
// grid (LL/32, 2*BB); 256 threads; 32-iteration delta tail
__global__ __launch_bounds__(256) void k4b_kernel(
    const float* __restrict__ Wdt0, const float* __restrict__ Wdt1,
    const float* __restrict__ bdt0, const float* __restrict__ bdt1)
{
    const int bz = blockIdx.y;
    const int br = bz >> 1;
    const int l0 = blockIdx.x * 32;
    const float* Wdt = br ? Wdt1 : Wdt0;
    const float* bdt = br ? bdt1 : bdt0;

    __shared__ float xds[40][33];
    __shared__ float Wdts[DI * RK];
    __shared__ float bdts[DI];

    const int tid = threadIdx.x;
    for (int i = tid; i < DI * RK; i += 256) Wdts[i] = Wdt[i];
    bdts[tid] = bdt[tid];

    const float* xa = g_xd0 + (size_t)bz * 40 * LL + l0;
    const float* xb = g_xd1 + (size_t)bz * 40 * LL + l0;
    for (int i = tid; i < 40 * 32; i += 256) {
        int r = i >> 5, c = i & 31;
        xds[r][c] = xa[(size_t)r * LL + c] + xb[(size_t)r * LL + c];
    }
    __syncthreads();

    // Bt/Ct blocked layout: (bz, l/16, n, l%16)
    {
        float* Bb = g_Bt + (size_t)bz * LL * NS;
        float* Cb = g_Ct + (size_t)bz * LL * NS;
        for (int i = tid; i < 512; i += 256) {
            int n = i >> 5, l = i & 31;
            size_t o = (size_t)(((l0 + l) >> 4) * NS + n) * 16 + (l & 15);
            Bb[o] = xds[8 + n][l];
            Cb[o] = xds[24 + n][l];
        }
    }
    // delta
    const int lcol = tid & 31, rg = tid >> 5;    // 32 cols x 8 row-groups
    float dtl[RK];
#pragma unroll
    for (int r = 0; r < RK; r++) dtl[r] = xds[r][lcol];
    float* dp = g_delta + (size_t)bz * DI * LL + l0 + lcol;
#pragma unroll 4
    for (int jj = 0; jj < 32; jj++) {
        int d = rg + jj * 8;
        float a = bdts[d];
#pragma unroll
        for (int r = 0; r < RK; r++)
            a = fmaf(Wdts[d * RK + r], dtl[r], a);
        float sp = fmaxf(a, 0.f) + __logf(1.f + __expf(-fabsf(a)));
        dp[(size_t)d * LL] = sp;
    }
}

// ---------------- K5a: chunk summaries ----------------
__global__ __launch_bounds__(128) void scan1_kernel(const float* __restrict__ A_log)
{
    const int lane = threadIdx.x & 31;
    const int hw = blockIdx.x * 8 + (threadIdx.x >> 5) * 2 + (lane >> 4);
    const int ch = hw >> 4;
    const int chunk = hw & 15;
    const int d  = ch & 255;
    const int bz = ch >> 8;
    const int n  = lane & 15;
    const int half = lane & 16;

    const float An = -__expf(A_log[d * NS + n]);
    const float* dl_p = g_delta + (size_t)ch * LL;
    const float* x_p  = g_xconv + (size_t)ch * LL;
    const float* B_p  = g_Bt + (size_t)bz * LL * NS;

    float h = 0.f, pa = 1.f;
    const int lbeg = chunk * TCH;
    for (int l0 = lbeg; l0 < lbeg + TCH; l0 += 16) {
        float dv = dl_p[l0 + n];
        float xv = x_p[l0 + n];
        float duv = dv * xv;
        float Bv[16];
        {
            const float* bb = &B_p[(size_t)((l0 >> 4) * NS + n) * 16];
            *(float4*)&Bv[0]  = *(const float4*)&bb[0];
            *(float4*)&Bv[4]  = *(const float4*)&bb[4];
            *(float4*)&Bv[8]  = *(const float4*)&bb[8];
            *(float4*)&Bv[12] = *(const float4*)&bb[12];
        }
#pragma unroll
        for (int s = 0; s < 16; s++) {
            float dl = __shfl_sync(0xffffffffu, dv,  half + s);
            float du = __shfl_sync(0xffffffffu, duv, half + s);
            float a = __expf(dl * An);
            h = fmaf(a, h, du * Bv[s]);
            pa *= a;
        }
    }
    size_t o = ((size_t)ch * NCH + chunk) * NS + n;
    g_P[o] = pa;
    g_E[o] = h;
}

// ---------------- K5b: stitch carries ----------------
__global__ __launch_bounds__(256) void scan2_kernel()
{
    int t = blockIdx.x * 256 + threadIdx.x;
    int ch = t >> 4;
    int n  = t & 15;
    float c = 0.f;
#pragma unroll
    for (int j = 0; j < NCH; j++) {
        size_t o = ((size_t)ch * NCH + j) * NS + n;
        g_c[o] = c;
        c = fmaf(g_P[o], c, g_E[o]);
    }
}

// ---------------- K5c: full scan + tree reduce + fused epilogue ----------------
__global__ __launch_bounds__(128) void scan3_kernel(
    const float* __restrict__ A_log,
    const float* __restrict__ D0, const float* __restrict__ D1)
{
    const int lane = threadIdx.x & 31;
    const int hw = blockIdx.x * 8 + (threadIdx.x >> 5) * 2 + (lane >> 4);
    const int ch = hw >> 4;
    const int chunk = hw & 15;
    const int br = ch >> 9;
    const int d  = ch & 255;
    const int bz = ch >> 8;
    const int n  = lane & 15;
    const int half = lane & 16;

    const float An = -__expf(A_log[d * NS + n]);
    const float Dd = (br ? D1 : D0)[d];

    const float* dl_p = g_delta + (size_t)ch * LL;
    const float* x_p  = g_xconv + (size_t)ch * LL;
    const float* z_p  = g_z     + (size_t)ch * LL;
    const float* B_p  = g_Bt + (size_t)bz * LL * NS;
    const float* C_p  = g_Ct + (size_t)bz * LL * NS;
    float* y_p = g_y + (size_t)ch * LL;

    float h = g_c[((size_t)ch * NCH + chunk) * NS + n];
    const int lbeg = chunk * TCH;
    for (int l0 = lbeg; l0 < lbeg + TCH; l0 += 16) {
        float dv = dl_p[l0 + n];
        float xv = x_p[l0 + n];
        float zv = z_p[l0 + n];
        float duv = dv * xv;
        float sv = zv / (1.f + __expf(-zv));
        float ev = Dd * xv;

        float Bv[16], Cv[16];
        {
            const size_t bo = (size_t)((l0 >> 4) * NS + n) * 16;
            const float* bb = &B_p[bo];
            const float* cc = &C_p[bo];
            *(float4*)&Bv[0]  = *(const float4*)&bb[0];
            *(float4*)&Bv[4]  = *(const float4*)&bb[4];
            *(float4*)&Bv[8]  = *(const float4*)&bb[8];
            *(float4*)&Bv[12] = *(const float4*)&bb[12];
            *(float4*)&Cv[0]  = *(const float4*)&cc[0];
            *(float4*)&Cv[4]  = *(const float4*)&cc[4];
            *(float4*)&Cv[8]  = *(const float4*)&cc[8];
            *(float4*)&Cv[12] = *(const float4*)&cc[12];
        }

        float v[16];
#pragma unroll
        for (int s = 0; s < 16; s++) {
            float dl = __shfl_sync(0xffffffffu, dv,  half + s);
            float du = __shfl_sync(0xffffffffu, duv, half + s);
            float a = __expf(dl * An);
            h = fmaf(a, h, du * Bv[s]);
            v[s] = h * Cv[s];
        }
        {
            bool hi = (n & 8) != 0;
#pragma unroll
            for (int j = 0; j < 8; j++) {
                float send = hi ? v[j] : v[j + 8];
                float recv = __shfl_xor_sync(0xffffffffu, send, 8);
                v[j] = (hi ? v[j + 8] : v[j]) + recv;
            }
        }
        {
            bool hi = (n & 4) != 0;
#pragma unroll
            for (int j = 0; j < 4; j++) {
                float send = hi ? v[j] : v[j + 4];
                float recv = __shfl_xor_sync(0xffffffffu, send, 4);
                v[j] = (hi ? v[j + 4] : v[j]) + recv;
            }
        }
        {
            bool hi = (n & 2) != 0;
#pragma unroll
            for (int j = 0; j < 2; j++) {
                float send = hi ? v[j] : v[j + 2];
                float recv = __shfl_xor_sync(0xffffffffu, send, 2);
                v[j] = (hi ? v[j + 2] : v[j]) + recv;
            }
        }
        {
            bool hi = (n & 1) != 0;
            float send = hi ? v[0] : v[1];
            float recv = __shfl_xor_sync(0xffffffffu, send, 1);
            v[0] = (hi ? v[1] : v[0]) + recv;
        }
        y_p[l0 + n] = (v[0] + ev) * sv;
    }
}

// ---------------- launch ----------------
extern "C" void kernel_launch(void* const* d_in, const int* in_sizes, int n_in,
                              void* d_out, int out_size)
{
    const float* pan     = (const float*)d_in[0];
    const float* ms      = (const float*)d_in[1];
    const float* nw_pan  = (const float*)d_in[2];
    const float* nb_pan  = (const float*)d_in[3];
    const float* nw_ms   = (const float*)d_in[4];
    const float* nb_ms   = (const float*)d_in[5];
    const float* Win_pan = (const float*)d_in[6];
    const float* Win_ms  = (const float*)d_in[7];
    const float* Wz_pan  = (const float*)d_in[8];
    const float* Wz_ms   = (const float*)d_in[9];
    const float* cw_pan  = (const float*)d_in[10];
    const float* cb_pan  = (const float*)d_in[11];
    const float* cw_ms   = (const float*)d_in[12];
    const float* cb_ms   = (const float*)d_in[13];
    const float* Wx_pan  = (const float*)d_in[14];
    const float* Wx_ms   = (const float*)d_in[15];
    const float* Wdt_pan = (const float*)d_in[16];
    const float* Wdt_ms  = (const float*)d_in[17];
    const float* bdt_pan = (const float*)d_in[18];
    const float* bdt_ms  = (const float*)d_in[19];
    const float* A_log   = (const float*)d_in[20];
    const float* D_pan   = (const float*)d_in[21];
    const float* D_ms    = (const float*)d_in[22];
    const float* Wout_pan= (const float*)d_in[23];
    const float* Wout_ms = (const float*)d_in[24];
    float* out = (float*)d_out;

    ln_kernel<<<dim3(LL / 32, BB, 2), 256>>>(pan, ms, nw_pan, nb_pan, nw_ms, nb_ms);

    gemm_kernel<CC, 0><<<dim3(LL / 128, 4, 2 * BB), 256>>>(
        Win_pan, Win_ms, Wz_pan, Wz_ms, nullptr);

    conv_kernel<<<(2 * BB * DI * LL / 4) / 256, 256>>>(cw_pan, cb_pan, cw_ms, cb_ms);

    xdbl_gemm_kernel<<<dim3(LL / 128, 2 * BB, 2), 256>>>(Wx_pan, Wx_ms);
    k4b_kernel<<<dim3(LL / 32, 2 * BB), 256>>>(Wdt_pan, Wdt_ms, bdt_pan, bdt_ms);

    scan1_kernel<<<(2 * BB * DI * NCH) / 8, 128>>>(A_log);
    scan2_kernel<<<(2 * BB * DI * NS) / 256, 256>>>();
    scan3_kernel<<<(2 * BB * DI * NCH) / 8, 128>>>(A_log, D_pan, D_ms);

    gemm_kernel<DI, 2><<<dim3(LL / 128, 1, 2 * BB), 256>>>(
        Wout_pan, Wout_ms, nullptr, nullptr, out);
}